// round 9
// baseline (speedup 1.0000x reference)
#include <cuda_runtime.h>
#include <cuda_bf16.h>
#include <math.h>
#include <stdint.h>

// Problem constants
#define B_   64
#define L_   500
#define F_   256
#define H_   4
#define DK_  64
#define BH_  (B_ * H_)      // 256
#define ROWS_ (B_ * L_)     // 32000

// -------- scratch (device globals; no allocations allowed) ---------
__device__ float g_Wc[F_ * F_];
__device__ float g_weight[(size_t)BH_ * L_ * DK_];      // relu(q Wc + b1), [b][h][l][d]
__device__ float g_vh[(size_t)BH_ * L_ * DK_];          // v w_vs,           [b][h][l][d]
__device__ float g_attnout[(size_t)ROWS_ * F_];
__device__ float g_x[(size_t)ROWS_ * F_];

// ---------- packed f32x2 FMA (PTX 8.6, plain sm_100+ family feature) ----------
__device__ __forceinline__ float2 ffma2(float2 a, float2 b, float2 c) {
    float2 d;
    asm("fma.rn.f32x2 %0, %1, %2, %3;"
        : "=l"(reinterpret_cast<unsigned long long&>(d))
        : "l"(reinterpret_cast<unsigned long long&>(a)),
          "l"(reinterpret_cast<unsigned long long&>(b)),
          "l"(reinterpret_cast<unsigned long long&>(c)));
    return d;
}

// ===================================================================
// Kernel 0: Wc[k][h*64+j] = sum_d w_qs[k][h*64+d] * w1[d][j]
// ===================================================================
__global__ void wc_kernel(const float* __restrict__ w_qs,
                          const float* __restrict__ w1) {
    int k = blockIdx.x;
    int n = threadIdx.x;
    int h = n >> 6, j = n & 63;
    const float* wq = w_qs + k * F_ + h * DK_;
    float acc = 0.f;
    #pragma unroll 8
    for (int d = 0; d < DK_; d++)
        acc += wq[d] * w1[d * DK_ + j];
    g_Wc[k * F_ + n] = acc;
}

// ===================================================================
// Kernel 1/2/4: tiled GEMM with f32x2 inner product
// grid: (nt=4, mt=8, b=64), block 256 (16x16 logical)
// MODE 0: out -> head layout [b][h=nt][l][d], no epilogue   (v proj)
// MODE 1: out -> head layout, +bias[d], relu                (q proj)
// MODE 2: out -> flat [b*l][f], + residual ep[b*l][f]       (fc)
// ===================================================================
template <int MODE>
__global__ void gemm_kernel(const float* __restrict__ A,
                            const float* __restrict__ Bw,
                            const float* __restrict__ ep,
                            float* __restrict__ Cout) {
    __shared__ float sA[64 * 20];
    __shared__ float sB[16 * 68];

    int nt = blockIdx.x, mt = blockIdx.y, b = blockIdx.z;
    int tid = threadIdx.x;
    int ty = tid >> 4, tx = tid & 15;
    int l0 = mt * 64;
    const float* Ab = A + (size_t)b * L_ * F_;

    float2 acc[4][2];
    #pragma unroll
    for (int i = 0; i < 4; i++) {
        acc[i][0] = make_float2(0.f, 0.f);
        acc[i][1] = make_float2(0.f, 0.f);
    }

    for (int k0 = 0; k0 < F_; k0 += 16) {
        {
            int r  = tid >> 2;
            int kv = (tid & 3) * 4;
            int l  = l0 + r;
            float4 v = make_float4(0.f, 0.f, 0.f, 0.f);
            if (l < L_) v = *(const float4*)(Ab + (size_t)l * F_ + k0 + kv);
            *(float4*)&sA[r * 20 + kv] = v;
        }
        {
            int kk = tid >> 4;
            int cv = (tid & 15) * 4;
            float4 v = *(const float4*)(Bw + (size_t)(k0 + kk) * F_ + nt * 64 + cv);
            *(float4*)&sB[kk * 68 + cv] = v;
        }
        __syncthreads();
        #pragma unroll
        for (int kk = 0; kk < 16; kk++) {
            float4 b4 = *(const float4*)&sB[kk * 68 + tx * 4];
            float2 b01 = make_float2(b4.x, b4.y);
            float2 b23 = make_float2(b4.z, b4.w);
            #pragma unroll
            for (int i = 0; i < 4; i++) {
                float a = sA[(ty * 4 + i) * 20 + kk];
                float2 ap = make_float2(a, a);
                acc[i][0] = ffma2(ap, b01, acc[i][0]);
                acc[i][1] = ffma2(ap, b23, acc[i][1]);
            }
        }
        __syncthreads();
    }

    #pragma unroll
    for (int i = 0; i < 4; i++) {
        int l = l0 + ty * 4 + i;
        if (l >= L_) continue;
        int c0 = tx * 4;
        float v0 = acc[i][0].x, v1 = acc[i][0].y, v2 = acc[i][1].x, v3 = acc[i][1].y;
        if (MODE == 1) {
            v0 = fmaxf(v0 + ep[c0 + 0], 0.f);
            v1 = fmaxf(v1 + ep[c0 + 1], 0.f);
            v2 = fmaxf(v2 + ep[c0 + 2], 0.f);
            v3 = fmaxf(v3 + ep[c0 + 3], 0.f);
        }
        if (MODE == 2) {
            const float4 rv = *(const float4*)(ep + ((size_t)b * L_ + l) * F_ + nt * 64 + c0);
            v0 += rv.x; v1 += rv.y; v2 += rv.z; v3 += rv.w;
        }
        float4 o = make_float4(v0, v1, v2, v3);
        if (MODE == 2) {
            *(float4*)(Cout + ((size_t)b * L_ + l) * F_ + nt * 64 + c0) = o;
        } else {
            *(float4*)(Cout + (((size_t)b * H_ + nt) * L_ + l) * (size_t)DK_ + c0) = o;
        }
    }
}

// ===================================================================
// Kernel 3: SIMT f32x2 attention, no-max softmax.
//   Block = 128 query rows (micro-tile 4r x 8c, 256 threads: ty 0..31, tx 0..7)
//   jt loop (8 x 64 keys):
//     S[r][j] = W[r][:] @ W2[:][j]  (+b2 via acc init; -1e30 masks j>=L)
//     p = expf(S); lsum[r] += sum_j p; sP[r][j] = p
//     O[r][d] += sP[r][:] @ V[:][d]   (register accumulator across jt)
//   final: cross-lane lsum reduce, O/lsum -> attnout
// ===================================================================
#define AST 68
__global__ void __launch_bounds__(256) attn_f2_kernel(
    const float* __restrict__ w2, const float* __restrict__ b2,
    const float* __restrict__ weight, const float* __restrict__ vh,
    float* __restrict__ attnout)
{
    extern __shared__ float sm[];
    float* sW  = sm;                    // [128][AST] weight rows
    float* sW2 = sW  + 128 * AST;       // [64][AST]  w2 (d, j)
    float* sV  = sW2 + 64 * AST;        // [64][AST]  vh (j, d)
    float* sP  = sV  + 64 * AST;        // [128][AST] probabilities
    float* sB2 = sP  + 128 * AST;       // [512]

    int tid = threadIdx.x;
    int ty = tid >> 3, tx = tid & 7;    // ty 0..31 (4 rows each), tx 0..7 (8 cols each)
    int bh = blockIdx.x, mt = blockIdx.y;
    int r0 = mt * 128;
    const float* wbase = weight + (size_t)bh * L_ * DK_;
    const float* vbase = vh + (size_t)bh * L_ * DK_;

    // b2 with -1e30 masking beyond L
    for (int i = tid; i < 512; i += 256)
        sB2[i] = (i < L_) ? b2[i] : -1.0e30f;

    // W tile [128][64] (8 float4 per thread)
    #pragma unroll
    for (int it = 0; it < 8; it++) {
        int idx = tid + it * 256;       // 0..2047
        int r = idx >> 4;               // 0..127
        int d4 = (idx & 15) * 4;
        int row = r0 + r;
        float4 v = make_float4(0.f, 0.f, 0.f, 0.f);
        if (row < L_) v = *(const float4*)(wbase + (size_t)row * DK_ + d4);
        *(float4*)&sW[r * AST + d4] = v;
    }

    float2 accO[4][4];
    float lsum[4];
    #pragma unroll
    for (int i = 0; i < 4; i++) {
        lsum[i] = 0.f;
        #pragma unroll
        for (int j = 0; j < 4; j++) accO[i][j] = make_float2(0.f, 0.f);
    }

    for (int jt = 0; jt < 8; jt++) {
        int j0 = jt * 64;
        __syncthreads();   // previous iteration consumers done (covers sW staging on jt=0)

        // stage w2 tile [d][j] (scalar: 500-stride rows are not float4-aligned)
        #pragma unroll
        for (int it = 0; it < 16; it++) {
            int idx = tid + it * 256;
            int d = idx >> 6, jj = idx & 63;
            int j = j0 + jj;
            sW2[d * AST + jj] = (j < L_) ? w2[(size_t)d * L_ + j] : 0.f;
        }
        // stage V tile [jj][d]
        #pragma unroll
        for (int it = 0; it < 4; it++) {
            int idx = tid + it * 256;
            int jj = idx >> 4;
            int d4 = (idx & 15) * 4;
            int j = j0 + jj;
            float4 v = make_float4(0.f, 0.f, 0.f, 0.f);
            if (j < L_) v = *(const float4*)(vbase + (size_t)j * DK_ + d4);
            *(float4*)&sV[jj * AST + d4] = v;
        }
        __syncthreads();

        // ---- S = W @ W2 (+ b2 init) ----
        float2 accS[4][4];
        {
            int jc = j0 + tx * 8;
            #pragma unroll
            for (int j2 = 0; j2 < 4; j2++) {
                float2 bb = make_float2(sB2[jc + j2 * 2], sB2[jc + j2 * 2 + 1]);
                #pragma unroll
                for (int i = 0; i < 4; i++) accS[i][j2] = bb;
            }
        }
        #pragma unroll 4
        for (int kk = 0; kk < 64; kk++) {
            float4 bA = *(const float4*)&sW2[kk * AST + tx * 8];
            float4 bB = *(const float4*)&sW2[kk * AST + tx * 8 + 4];
            float2 p0 = make_float2(bA.x, bA.y), p1 = make_float2(bA.z, bA.w);
            float2 p2 = make_float2(bB.x, bB.y), p3 = make_float2(bB.z, bB.w);
            #pragma unroll
            for (int i = 0; i < 4; i++) {
                float a = sW[(ty * 4 + i) * AST + kk];
                float2 ap = make_float2(a, a);
                accS[i][0] = ffma2(ap, p0, accS[i][0]);
                accS[i][1] = ffma2(ap, p1, accS[i][1]);
                accS[i][2] = ffma2(ap, p2, accS[i][2]);
                accS[i][3] = ffma2(ap, p3, accS[i][3]);
            }
        }

        // ---- p = exp(s), accumulate row sums, stage into sP ----
        #pragma unroll
        for (int i = 0; i < 4; i++) {
            float p0 = __expf(accS[i][0].x), p1 = __expf(accS[i][0].y);
            float p2 = __expf(accS[i][1].x), p3 = __expf(accS[i][1].y);
            float p4 = __expf(accS[i][2].x), p5 = __expf(accS[i][2].y);
            float p6 = __expf(accS[i][3].x), p7 = __expf(accS[i][3].y);
            lsum[i] += ((p0 + p1) + (p2 + p3)) + ((p4 + p5) + (p6 + p7));
            float* dst = &sP[(ty * 4 + i) * AST + tx * 8];
            *(float4*)dst       = make_float4(p0, p1, p2, p3);
            *(float4*)(dst + 4) = make_float4(p4, p5, p6, p7);
        }
        __syncthreads();

        // ---- O += P @ V ----
        #pragma unroll 4
        for (int kk = 0; kk < 64; kk++) {
            float4 vA = *(const float4*)&sV[kk * AST + tx * 8];
            float4 vB = *(const float4*)&sV[kk * AST + tx * 8 + 4];
            float2 q0 = make_float2(vA.x, vA.y), q1 = make_float2(vA.z, vA.w);
            float2 q2 = make_float2(vB.x, vB.y), q3 = make_float2(vB.z, vB.w);
            #pragma unroll
            for (int i = 0; i < 4; i++) {
                float p = sP[(ty * 4 + i) * AST + kk];
                float2 pp = make_float2(p, p);
                accO[i][0] = ffma2(pp, q0, accO[i][0]);
                accO[i][1] = ffma2(pp, q1, accO[i][1]);
                accO[i][2] = ffma2(pp, q2, accO[i][2]);
                accO[i][3] = ffma2(pp, q3, accO[i][3]);
            }
        }
    }

    // ---- reduce lsum across the 8 tx lanes (same 4 rows), normalize, store ----
    int b = bh >> 2, h = bh & 3;
    #pragma unroll
    for (int i = 0; i < 4; i++) {
        float s = lsum[i];
        #pragma unroll
        for (int off = 1; off < 8; off <<= 1)
            s += __shfl_xor_sync(0xffffffffu, s, off);
        int row = r0 + ty * 4 + i;
        if (row < L_) {
            float inv = 1.f / s;
            float* dst = attnout + ((size_t)b * L_ + row) * F_ + h * DK_ + tx * 8;
            *(float4*)dst = make_float4(accO[i][0].x * inv, accO[i][0].y * inv,
                                        accO[i][1].x * inv, accO[i][1].y * inv);
            *(float4*)(dst + 4) = make_float4(accO[i][2].x * inv, accO[i][2].y * inv,
                                              accO[i][3].x * inv, accO[i][3].y * inv);
        }
    }
}
#define ATTN_SMEM ((128 * AST + 64 * AST + 64 * AST + 128 * AST + 512) * (int)sizeof(float))

// ===================================================================
// Kernel 5: LayerNorm per row
// ===================================================================
__global__ void ln_kernel(const float* __restrict__ x,
                          const float* __restrict__ gam,
                          const float* __restrict__ bet,
                          float* __restrict__ out) {
    int row = blockIdx.x;
    int tid = threadIdx.x;
    float v = x[(size_t)row * F_ + tid];
    float s = v, s2 = v * v;
    #pragma unroll
    for (int off = 16; off; off >>= 1) {
        s  += __shfl_xor_sync(0xffffffffu, s,  off);
        s2 += __shfl_xor_sync(0xffffffffu, s2, off);
    }
    __shared__ float ws[8], ws2[8];
    int w = tid >> 5, lane = tid & 31;
    if (lane == 0) { ws[w] = s; ws2[w] = s2; }
    __syncthreads();
    float ts = 0.f, ts2 = 0.f;
    #pragma unroll
    for (int i = 0; i < 8; i++) { ts += ws[i]; ts2 += ws2[i]; }
    float mu  = ts * (1.f / F_);
    float var = ts2 * (1.f / F_) - mu * mu;
    float r = rsqrtf(var + 1e-6f);
    out[(size_t)row * F_ + tid] = (v - mu) * r * gam[tid] + bet[tid];
}

// ===================================================================
// launch
// ===================================================================
extern "C" void kernel_launch(void* const* d_in, const int* in_sizes, int n_in,
                              void* d_out, int out_size) {
    (void)in_sizes; (void)n_in; (void)out_size;
    const float* q    = (const float*)d_in[0];
    const float* v    = (const float*)d_in[2];
    const float* w_qs = (const float*)d_in[3];
    const float* w_vs = (const float*)d_in[4];
    const float* w1   = (const float*)d_in[5];
    const float* b1   = (const float*)d_in[6];
    const float* w2   = (const float*)d_in[7];
    const float* b2   = (const float*)d_in[8];
    const float* fc_w = (const float*)d_in[9];
    const float* ln_g = (const float*)d_in[10];
    const float* ln_b = (const float*)d_in[11];
    float* out = (float*)d_out;

    float *Wc_p, *weight_p, *vh_p, *attn_p, *x_p;
    cudaGetSymbolAddress((void**)&Wc_p,     g_Wc);
    cudaGetSymbolAddress((void**)&weight_p, g_weight);
    cudaGetSymbolAddress((void**)&vh_p,     g_vh);
    cudaGetSymbolAddress((void**)&attn_p,   g_attnout);
    cudaGetSymbolAddress((void**)&x_p,      g_x);

    cudaFuncSetAttribute(attn_f2_kernel, cudaFuncAttributeMaxDynamicSharedMemorySize, ATTN_SMEM);

    // 0) combined q-projection weight
    wc_kernel<<<256, 256>>>(w_qs, w1);

    dim3 gg(4, 8, 64);
    // 1) weight = relu(q @ Wc + b1) -> [b][h][l][d]
    gemm_kernel<1><<<gg, 256>>>(q, Wc_p, b1, weight_p);
    // 2) vh = v @ w_vs -> [b][h][l][d]
    gemm_kernel<0><<<gg, 256>>>(v, w_vs, nullptr, vh_p);
    // 3) fused synthesizer attention (f32x2, no-max softmax)
    attn_f2_kernel<<<dim3(BH_, 4), 256, ATTN_SMEM>>>(w2, b2, weight_p, vh_p, attn_p);
    // 4) x = attnout @ fc_w + q
    gemm_kernel<2><<<gg, 256>>>(attn_p, fc_w, q, x_p);
    // 5) LayerNorm
    ln_kernel<<<ROWS_, 256>>>(x_p, ln_g, ln_b, out);
}

// round 11
// speedup vs baseline: 1.2379x; 1.2379x over previous
#include <cuda_runtime.h>
#include <cuda_bf16.h>
#include <math.h>
#include <stdint.h>

// Problem constants
#define B_   64
#define L_   500
#define F_   256
#define H_   4
#define DK_  64
#define BH_  (B_ * H_)      // 256
#define ROWS_ (B_ * L_)     // 32000

// -------- scratch (device globals; no allocations allowed) ---------
__device__ float g_Wc[F_ * F_];
__device__ float g_weight[(size_t)BH_ * L_ * DK_];      // relu(q Wc + b1), [b][h][l][d]
__device__ float g_vh[(size_t)BH_ * L_ * DK_];          // v w_vs,           [b][h][l][d]
__device__ float g_attnout[(size_t)ROWS_ * F_];
__device__ float g_x[(size_t)ROWS_ * F_];

// ---------- packed f32x2 FMA ----------
__device__ __forceinline__ float2 ffma2(float2 a, float2 b, float2 c) {
    float2 d;
    asm("fma.rn.f32x2 %0, %1, %2, %3;"
        : "=l"(reinterpret_cast<unsigned long long&>(d))
        : "l"(reinterpret_cast<unsigned long long&>(a)),
          "l"(reinterpret_cast<unsigned long long&>(b)),
          "l"(reinterpret_cast<unsigned long long&>(c)));
    return d;
}

// ===================================================================
// Kernel 0: Wc[k][h*64+j] = sum_d w_qs[k][h*64+d] * w1[d][j]
// ===================================================================
__global__ void wc_kernel(const float* __restrict__ w_qs,
                          const float* __restrict__ w1) {
    int k = blockIdx.x;
    int n = threadIdx.x;
    int h = n >> 6, j = n & 63;
    const float* wq = w_qs + k * F_ + h * DK_;
    float acc = 0.f;
    #pragma unroll 8
    for (int d = 0; d < DK_; d++)
        acc += wq[d] * w1[d * DK_ + j];
    g_Wc[k * F_ + n] = acc;
}

// ===================================================================
// Kernel 1/2/4: tiled GEMM with f32x2 inner product (unchanged)
// ===================================================================
template <int MODE>
__global__ void gemm_kernel(const float* __restrict__ A,
                            const float* __restrict__ Bw,
                            const float* __restrict__ ep,
                            float* __restrict__ Cout) {
    __shared__ float sA[64 * 20];
    __shared__ float sB[16 * 68];

    int nt = blockIdx.x, mt = blockIdx.y, b = blockIdx.z;
    int tid = threadIdx.x;
    int ty = tid >> 4, tx = tid & 15;
    int l0 = mt * 64;
    const float* Ab = A + (size_t)b * L_ * F_;

    float2 acc[4][2];
    #pragma unroll
    for (int i = 0; i < 4; i++) {
        acc[i][0] = make_float2(0.f, 0.f);
        acc[i][1] = make_float2(0.f, 0.f);
    }

    for (int k0 = 0; k0 < F_; k0 += 16) {
        {
            int r  = tid >> 2;
            int kv = (tid & 3) * 4;
            int l  = l0 + r;
            float4 v = make_float4(0.f, 0.f, 0.f, 0.f);
            if (l < L_) v = *(const float4*)(Ab + (size_t)l * F_ + k0 + kv);
            *(float4*)&sA[r * 20 + kv] = v;
        }
        {
            int kk = tid >> 4;
            int cv = (tid & 15) * 4;
            float4 v = *(const float4*)(Bw + (size_t)(k0 + kk) * F_ + nt * 64 + cv);
            *(float4*)&sB[kk * 68 + cv] = v;
        }
        __syncthreads();
        #pragma unroll
        for (int kk = 0; kk < 16; kk++) {
            float4 b4 = *(const float4*)&sB[kk * 68 + tx * 4];
            float2 b01 = make_float2(b4.x, b4.y);
            float2 b23 = make_float2(b4.z, b4.w);
            #pragma unroll
            for (int i = 0; i < 4; i++) {
                float a = sA[(ty * 4 + i) * 20 + kk];
                float2 ap = make_float2(a, a);
                acc[i][0] = ffma2(ap, b01, acc[i][0]);
                acc[i][1] = ffma2(ap, b23, acc[i][1]);
            }
        }
        __syncthreads();
    }

    #pragma unroll
    for (int i = 0; i < 4; i++) {
        int l = l0 + ty * 4 + i;
        if (l >= L_) continue;
        int c0 = tx * 4;
        float v0 = acc[i][0].x, v1 = acc[i][0].y, v2 = acc[i][1].x, v3 = acc[i][1].y;
        if (MODE == 1) {
            v0 = fmaxf(v0 + ep[c0 + 0], 0.f);
            v1 = fmaxf(v1 + ep[c0 + 1], 0.f);
            v2 = fmaxf(v2 + ep[c0 + 2], 0.f);
            v3 = fmaxf(v3 + ep[c0 + 3], 0.f);
        }
        if (MODE == 2) {
            const float4 rv = *(const float4*)(ep + ((size_t)b * L_ + l) * F_ + nt * 64 + c0);
            v0 += rv.x; v1 += rv.y; v2 += rv.z; v3 += rv.w;
        }
        float4 o = make_float4(v0, v1, v2, v3);
        if (MODE == 2) {
            *(float4*)(Cout + ((size_t)b * L_ + l) * F_ + nt * 64 + c0) = o;
        } else {
            *(float4*)(Cout + (((size_t)b * H_ + nt) * L_ + l) * (size_t)DK_ + c0) = o;
        }
    }
}

// ===================================================================
// Kernel 3 (v3): attention, 128x128 key tiles, 8x8 micro-tile,
// transposed staging for conflict-free vectorized fragments.
//   thread: ry = tid&15 (rows ry*4 and 64+ry*4), jx = tid>>4
//   S loop over d=64:  S[8r][8j] += WT[d][r] * W2[d][j]
//   p = exp(S + b2)  (no-max; b2=-1e30 masks j>=L)
//   P -> sPT[j][r]   (transposed, quad-group conflict-free)
//   O loop over j=128: O[8r][4d] += PT[j][r] * V[j][d]  (acc across jt)
//   end: lsum reduced once via smem; O/lsum -> attnout
// ===================================================================
// smem layout (floats)
#define A_WT   0                      // [64][128]
#define A_W2   (A_WT + 64 * 128)      // [64][128]
#define A_V    (A_W2 + 64 * 128)      // [128][64]
#define A_PT   (A_V  + 128 * 64)      // [128][128]
#define A_B2   (A_PT + 128 * 128)     // [512]
#define A_TOT  (A_B2 + 512)           // 41472 floats = 165888 B

__global__ void __launch_bounds__(256, 1) attn_v3_kernel(
    const float* __restrict__ w2, const float* __restrict__ b2,
    const float* __restrict__ weight, const float* __restrict__ vh,
    float* __restrict__ attnout)
{
    extern __shared__ float sm[];
    int tid = threadIdx.x;
    int ry = tid & 15, jx = tid >> 4;
    int bh = blockIdx.x, mt = blockIdx.y;
    int r0 = mt * 128;
    const float* wbase = weight + (size_t)bh * L_ * DK_;
    const float* vbase = vh + (size_t)bh * L_ * DK_;

    // b2 (+ -1e30 mask beyond L)
    for (int i = tid; i < 512; i += 256)
        sm[A_B2 + i] = (i < L_) ? b2[i] : -1.0e30f;

    // stage W transposed: sWT[d][r]  (once per block)
    #pragma unroll
    for (int it = 0; it < 8; it++) {
        int idx = tid + it * 256;       // 0..2047
        int r = idx >> 4;               // 0..127
        int d4 = (idx & 15) * 4;
        int row = r0 + r;
        float4 v = make_float4(0.f, 0.f, 0.f, 0.f);
        if (row < L_) v = *(const float4*)(wbase + (size_t)row * DK_ + d4);
        sm[A_WT + (d4 + 0) * 128 + r] = v.x;
        sm[A_WT + (d4 + 1) * 128 + r] = v.y;
        sm[A_WT + (d4 + 2) * 128 + r] = v.z;
        sm[A_WT + (d4 + 3) * 128 + r] = v.w;
    }

    float2 accO[2][4][2];
    float lsumP[2][4];
    #pragma unroll
    for (int h2 = 0; h2 < 2; h2++)
        #pragma unroll
        for (int rr = 0; rr < 4; rr++) {
            lsumP[h2][rr] = 0.f;
            accO[h2][rr][0] = make_float2(0.f, 0.f);
            accO[h2][rr][1] = make_float2(0.f, 0.f);
        }

    for (int jt = 0; jt < 4; jt++) {
        int j0 = jt * 128;
        __syncthreads();   // prev O-loop consumers done (covers sWT/sB2 on jt=0)

        // stage w2 tile [d][j]
        #pragma unroll
        for (int it = 0; it < 32; it++) {
            int idx = tid + it * 256;   // 0..8191
            int d = idx >> 7, jj = idx & 127;
            int j = j0 + jj;
            sm[A_W2 + d * 128 + jj] = (j < L_) ? w2[(size_t)d * L_ + j] : 0.f;
        }
        // stage V tile [j][d]
        #pragma unroll
        for (int it = 0; it < 8; it++) {
            int idx = tid + it * 256;   // 0..2047
            int jj = idx >> 4;
            int d4 = (idx & 15) * 4;
            int j = j0 + jj;
            float4 v = make_float4(0.f, 0.f, 0.f, 0.f);
            if (j < L_) v = *(const float4*)(vbase + (size_t)j * DK_ + d4);
            *(float4*)&sm[A_V + jj * 64 + d4] = v;
        }
        __syncthreads();

        // ---- S = WT^T @ W2 (+ b2 init) ----
        float2 accS[2][4][4];
        {
            float4 bb0 = *(const float4*)&sm[A_B2 + j0 + jx * 8];
            float4 bb1 = *(const float4*)&sm[A_B2 + j0 + jx * 8 + 4];
            float2 bc[4] = { make_float2(bb0.x, bb0.y), make_float2(bb0.z, bb0.w),
                             make_float2(bb1.x, bb1.y), make_float2(bb1.z, bb1.w) };
            #pragma unroll
            for (int h2 = 0; h2 < 2; h2++)
                #pragma unroll
                for (int rr = 0; rr < 4; rr++)
                    #pragma unroll
                    for (int cc = 0; cc < 4; cc++)
                        accS[h2][rr][cc] = bc[cc];
        }
        #pragma unroll 4
        for (int d = 0; d < 64; d++) {
            float4 a0 = *(const float4*)&sm[A_WT + d * 128 + ry * 4];
            float4 a1 = *(const float4*)&sm[A_WT + d * 128 + 64 + ry * 4];
            float4 b0 = *(const float4*)&sm[A_W2 + d * 128 + jx * 8];
            float4 b1 = *(const float4*)&sm[A_W2 + d * 128 + jx * 8 + 4];
            float2 bc0 = make_float2(b0.x, b0.y), bc1 = make_float2(b0.z, b0.w);
            float2 bc2 = make_float2(b1.x, b1.y), bc3 = make_float2(b1.z, b1.w);
            float av[2][4] = { {a0.x, a0.y, a0.z, a0.w}, {a1.x, a1.y, a1.z, a1.w} };
            #pragma unroll
            for (int h2 = 0; h2 < 2; h2++)
                #pragma unroll
                for (int rr = 0; rr < 4; rr++) {
                    float2 ap = make_float2(av[h2][rr], av[h2][rr]);
                    accS[h2][rr][0] = ffma2(ap, bc0, accS[h2][rr][0]);
                    accS[h2][rr][1] = ffma2(ap, bc1, accS[h2][rr][1]);
                    accS[h2][rr][2] = ffma2(ap, bc2, accS[h2][rr][2]);
                    accS[h2][rr][3] = ffma2(ap, bc3, accS[h2][rr][3]);
                }
        }

        // ---- p = exp(s), accumulate partial row sums (in place) ----
        #pragma unroll
        for (int h2 = 0; h2 < 2; h2++)
            #pragma unroll
            for (int rr = 0; rr < 4; rr++) {
                float s = 0.f;
                #pragma unroll
                for (int cc = 0; cc < 4; cc++) {
                    float px = __expf(accS[h2][rr][cc].x);
                    float py = __expf(accS[h2][rr][cc].y);
                    accS[h2][rr][cc] = make_float2(px, py);
                    s += px + py;
                }
                lsumP[h2][rr] += s;
            }

        // ---- transpose-store P: sPT[j][r] (quad-group, conflict-free) ----
        #pragma unroll
        for (int jj = 0; jj < 8; jj++) {
            int cc = jj >> 1;
            float4 c0, c1;
            if (jj & 1) {
                c0 = make_float4(accS[0][0][cc].y, accS[0][1][cc].y, accS[0][2][cc].y, accS[0][3][cc].y);
                c1 = make_float4(accS[1][0][cc].y, accS[1][1][cc].y, accS[1][2][cc].y, accS[1][3][cc].y);
            } else {
                c0 = make_float4(accS[0][0][cc].x, accS[0][1][cc].x, accS[0][2][cc].x, accS[0][3][cc].x);
                c1 = make_float4(accS[1][0][cc].x, accS[1][1][cc].x, accS[1][2][cc].x, accS[1][3][cc].x);
            }
            int j = jx * 8 + jj;
            *(float4*)&sm[A_PT + j * 128 + ry * 4]      = c0;
            *(float4*)&sm[A_PT + j * 128 + 64 + ry * 4] = c1;
        }
        __syncthreads();

        // ---- O += P^T(as [j][r]) @ V ----
        #pragma unroll 4
        for (int j = 0; j < 128; j++) {
            float4 a0 = *(const float4*)&sm[A_PT + j * 128 + ry * 4];
            float4 a1 = *(const float4*)&sm[A_PT + j * 128 + 64 + ry * 4];
            float4 bv = *(const float4*)&sm[A_V + j * 64 + jx * 4];
            float2 q0 = make_float2(bv.x, bv.y), q1 = make_float2(bv.z, bv.w);
            float av[2][4] = { {a0.x, a0.y, a0.z, a0.w}, {a1.x, a1.y, a1.z, a1.w} };
            #pragma unroll
            for (int h2 = 0; h2 < 2; h2++)
                #pragma unroll
                for (int rr = 0; rr < 4; rr++) {
                    float2 pp = make_float2(av[h2][rr], av[h2][rr]);
                    accO[h2][rr][0] = ffma2(pp, q0, accO[h2][rr][0]);
                    accO[h2][rr][1] = ffma2(pp, q1, accO[h2][rr][1]);
                }
        }
    }

    // ---- final lsum reduction (once) + normalize + store ----
    __syncthreads();
    float* sRed = &sm[A_W2];   // reuse w2 region: [128][17]
    #pragma unroll
    for (int h2 = 0; h2 < 2; h2++)
        #pragma unroll
        for (int rr = 0; rr < 4; rr++) {
            int rt = h2 * 64 + ry * 4 + rr;
            sRed[rt * 17 + jx] = lsumP[h2][rr];
        }
    __syncthreads();
    float* sInv = &sm[A_B2];   // reuse b2 region
    if (tid < 128) {
        float s = 0.f;
        #pragma unroll
        for (int x = 0; x < 16; x++) s += sRed[tid * 17 + x];
        sInv[tid] = 1.f / s;
    }
    __syncthreads();

    int b = bh >> 2, h = bh & 3;
    #pragma unroll
    for (int h2 = 0; h2 < 2; h2++)
        #pragma unroll
        for (int rr = 0; rr < 4; rr++) {
            int rt = h2 * 64 + ry * 4 + rr;
            int row = r0 + rt;
            if (row < L_) {
                float inv = sInv[rt];
                float4 o = make_float4(accO[h2][rr][0].x * inv, accO[h2][rr][0].y * inv,
                                       accO[h2][rr][1].x * inv, accO[h2][rr][1].y * inv);
                *(float4*)(attnout + ((size_t)b * L_ + row) * F_ + h * DK_ + jx * 4) = o;
            }
        }
}
#define ATTN_SMEM (A_TOT * (int)sizeof(float))

// ===================================================================
// Kernel 5: LayerNorm per row
// ===================================================================
__global__ void ln_kernel(const float* __restrict__ x,
                          const float* __restrict__ gam,
                          const float* __restrict__ bet,
                          float* __restrict__ out) {
    int row = blockIdx.x;
    int tid = threadIdx.x;
    float v = x[(size_t)row * F_ + tid];
    float s = v, s2 = v * v;
    #pragma unroll
    for (int off = 16; off; off >>= 1) {
        s  += __shfl_xor_sync(0xffffffffu, s,  off);
        s2 += __shfl_xor_sync(0xffffffffu, s2, off);
    }
    __shared__ float ws[8], ws2[8];
    int w = tid >> 5, lane = tid & 31;
    if (lane == 0) { ws[w] = s; ws2[w] = s2; }
    __syncthreads();
    float ts = 0.f, ts2 = 0.f;
    #pragma unroll
    for (int i = 0; i < 8; i++) { ts += ws[i]; ts2 += ws2[i]; }
    float mu  = ts * (1.f / F_);
    float var = ts2 * (1.f / F_) - mu * mu;
    float r = rsqrtf(var + 1e-6f);
    out[(size_t)row * F_ + tid] = (v - mu) * r * gam[tid] + bet[tid];
}

// ===================================================================
// launch
// ===================================================================
extern "C" void kernel_launch(void* const* d_in, const int* in_sizes, int n_in,
                              void* d_out, int out_size) {
    (void)in_sizes; (void)n_in; (void)out_size;
    const float* q    = (const float*)d_in[0];
    const float* v    = (const float*)d_in[2];
    const float* w_qs = (const float*)d_in[3];
    const float* w_vs = (const float*)d_in[4];
    const float* w1   = (const float*)d_in[5];
    const float* b1   = (const float*)d_in[6];
    const float* w2   = (const float*)d_in[7];
    const float* b2   = (const float*)d_in[8];
    const float* fc_w = (const float*)d_in[9];
    const float* ln_g = (const float*)d_in[10];
    const float* ln_b = (const float*)d_in[11];
    float* out = (float*)d_out;

    float *Wc_p, *weight_p, *vh_p, *attn_p, *x_p;
    cudaGetSymbolAddress((void**)&Wc_p,     g_Wc);
    cudaGetSymbolAddress((void**)&weight_p, g_weight);
    cudaGetSymbolAddress((void**)&vh_p,     g_vh);
    cudaGetSymbolAddress((void**)&attn_p,   g_attnout);
    cudaGetSymbolAddress((void**)&x_p,      g_x);

    cudaFuncSetAttribute(attn_v3_kernel, cudaFuncAttributeMaxDynamicSharedMemorySize, ATTN_SMEM);

    // 0) combined q-projection weight
    wc_kernel<<<256, 256>>>(w_qs, w1);

    dim3 gg(4, 8, 64);
    // 1) weight = relu(q @ Wc + b1) -> [b][h][l][d]
    gemm_kernel<1><<<gg, 256>>>(q, Wc_p, b1, weight_p);
    // 2) vh = v @ w_vs -> [b][h][l][d]
    gemm_kernel<0><<<gg, 256>>>(v, w_vs, nullptr, vh_p);
    // 3) fused synthesizer attention (v3: 8x8 tiles, conflict-free frags)
    attn_v3_kernel<<<dim3(BH_, 4), 256, ATTN_SMEM>>>(w2, b2, weight_p, vh_p, attn_p);
    // 4) x = attnout @ fc_w + q
    gemm_kernel<2><<<gg, 256>>>(attn_p, fc_w, q, x_p);
    // 5) LayerNorm
    ln_kernel<<<ROWS_, 256>>>(x_p, ln_g, ln_b, out);
}

// round 14
// speedup vs baseline: 1.2479x; 1.0080x over previous
#include <cuda_runtime.h>
#include <cuda_bf16.h>
#include <math.h>
#include <stdint.h>

// Problem constants
#define B_   64
#define L_   500
#define F_   256
#define H_   4
#define DK_  64
#define BH_  (B_ * H_)      // 256
#define ROWS_ (B_ * L_)     // 32000

// -------- scratch (device globals; no allocations allowed) ---------
__device__ float g_Wc[F_ * F_];
__device__ float g_weight[(size_t)BH_ * L_ * DK_];      // relu(q Wc + b1), [b][h][l][d]
__device__ float g_vh[(size_t)BH_ * L_ * DK_];          // v w_vs,           [b][h][l][d]
__device__ float g_attnout[(size_t)ROWS_ * F_];         // attention output  [b*l][f]

// ---------- packed f32x2 FMA ----------
__device__ __forceinline__ float2 ffma2(float2 a, float2 b, float2 c) {
    float2 d;
    asm("fma.rn.f32x2 %0, %1, %2, %3;"
        : "=l"(reinterpret_cast<unsigned long long&>(d))
        : "l"(reinterpret_cast<unsigned long long&>(a)),
          "l"(reinterpret_cast<unsigned long long&>(b)),
          "l"(reinterpret_cast<unsigned long long&>(c)));
    return d;
}

// ===================================================================
// Kernel 0: Wc[k][h*64+j] = sum_d w_qs[k][h*64+d] * w1[d][j]
// ===================================================================
__global__ void wc_kernel(const float* __restrict__ w_qs,
                          const float* __restrict__ w1) {
    int k = blockIdx.x;
    int n = threadIdx.x;
    int h = n >> 6, j = n & 63;
    const float* wq = w_qs + k * F_ + h * DK_;
    float acc = 0.f;
    #pragma unroll 8
    for (int d = 0; d < DK_; d++)
        acc += wq[d] * w1[d * DK_ + j];
    g_Wc[k * F_ + n] = acc;
}

// ===================================================================
// Kernel 1/2: projection GEMM v3 — C[128r x 128c] tiles, 8x8 micro.
// grid (ct=2, mt=4, b=64), 256 threads, smem 64KB, 2 CTAs/SM.
//   ry = tid&15 -> rows ry*4 & 64+ry*4 ; cx = tid>>4 -> cols cx*8
//   A staged TRANSPOSED sAT[k][r] (r-consecutive STS = conflict-free)
//   B staged natural sB[k][c]
// MODE 0: out head layout, no epilogue   (v proj)
// MODE 1: out head layout, +b1[d], relu  (q proj)
// ===================================================================
template <int MODE>
__global__ void __launch_bounds__(256, 2) gemm_v3_kernel(
    const float* __restrict__ A, const float* __restrict__ Bw,
    const float* __restrict__ ep, float* __restrict__ Cout)
{
    extern __shared__ float sm[];
    float* sAT = sm;              // [64][128]
    float* sB  = sm + 64 * 128;   // [64][128]

    int tid = threadIdx.x;
    int ry = tid & 15, cx = tid >> 4;
    int ct = blockIdx.x, mt = blockIdx.y, b = blockIdx.z;
    int r0 = mt * 128, c0t = ct * 128;
    const float* Ab = A + (size_t)b * L_ * F_;

    float2 acc[2][4][4];
    #pragma unroll
    for (int h2 = 0; h2 < 2; h2++)
        #pragma unroll
        for (int rr = 0; rr < 4; rr++)
            #pragma unroll
            for (int cc = 0; cc < 4; cc++)
                acc[h2][rr][cc] = make_float2(0.f, 0.f);

    for (int k0 = 0; k0 < F_; k0 += 64) {
        __syncthreads();
        // stage A transposed: 2048 float4 slots; r = idx&127 (lane-consecutive
        // -> conflict-free STS), kb = idx>>7
        #pragma unroll
        for (int it = 0; it < 8; it++) {
            int idx = tid + it * 256;
            int r = idx & 127, kb = idx >> 7;       // kb 0..15
            int row = r0 + r;
            float4 v = make_float4(0.f, 0.f, 0.f, 0.f);
            if (row < L_) v = *(const float4*)(Ab + (size_t)row * F_ + k0 + kb * 4);
            sAT[(kb * 4 + 0) * 128 + r] = v.x;
            sAT[(kb * 4 + 1) * 128 + r] = v.y;
            sAT[(kb * 4 + 2) * 128 + r] = v.z;
            sAT[(kb * 4 + 3) * 128 + r] = v.w;
        }
        // stage B natural: kk = idx>>5, c4 = (idx&31)*4 (coalesced both ways)
        #pragma unroll
        for (int it = 0; it < 8; it++) {
            int idx = tid + it * 256;
            int kk = idx >> 5, c4 = (idx & 31) * 4;
            float4 v = *(const float4*)(Bw + (size_t)(k0 + kk) * F_ + c0t + c4);
            *(float4*)&sB[kk * 128 + c4] = v;
        }
        __syncthreads();

        #pragma unroll 8
        for (int kk = 0; kk < 64; kk++) {
            float4 a0 = *(const float4*)&sAT[kk * 128 + ry * 4];
            float4 a1 = *(const float4*)&sAT[kk * 128 + 64 + ry * 4];
            float4 b0 = *(const float4*)&sB[kk * 128 + cx * 8];
            float4 b1 = *(const float4*)&sB[kk * 128 + cx * 8 + 4];
            float2 bc0 = make_float2(b0.x, b0.y), bc1 = make_float2(b0.z, b0.w);
            float2 bc2 = make_float2(b1.x, b1.y), bc3 = make_float2(b1.z, b1.w);
            float av[2][4] = { {a0.x, a0.y, a0.z, a0.w}, {a1.x, a1.y, a1.z, a1.w} };
            #pragma unroll
            for (int h2 = 0; h2 < 2; h2++)
                #pragma unroll
                for (int rr = 0; rr < 4; rr++) {
                    float2 ap = make_float2(av[h2][rr], av[h2][rr]);
                    acc[h2][rr][0] = ffma2(ap, bc0, acc[h2][rr][0]);
                    acc[h2][rr][1] = ffma2(ap, bc1, acc[h2][rr][1]);
                    acc[h2][rr][2] = ffma2(ap, bc2, acc[h2][rr][2]);
                    acc[h2][rr][3] = ffma2(ap, bc3, acc[h2][rr][3]);
                }
        }
    }

    // epilogue: head layout [b][h][row][d]
    int c_lo = c0t + cx * 8;
    int h = c_lo >> 6, d = c_lo & 63;
    float4 bi0 = make_float4(0.f, 0.f, 0.f, 0.f), bi1 = bi0;
    if (MODE == 1) {
        bi0 = *(const float4*)(ep + d);
        bi1 = *(const float4*)(ep + d + 4);
    }
    #pragma unroll
    for (int h2 = 0; h2 < 2; h2++)
        #pragma unroll
        for (int rr = 0; rr < 4; rr++) {
            int row = r0 + h2 * 64 + ry * 4 + rr;
            if (row >= L_) continue;
            float4 o0 = make_float4(acc[h2][rr][0].x, acc[h2][rr][0].y,
                                    acc[h2][rr][1].x, acc[h2][rr][1].y);
            float4 o1 = make_float4(acc[h2][rr][2].x, acc[h2][rr][2].y,
                                    acc[h2][rr][3].x, acc[h2][rr][3].y);
            if (MODE == 1) {
                o0.x = fmaxf(o0.x + bi0.x, 0.f); o0.y = fmaxf(o0.y + bi0.y, 0.f);
                o0.z = fmaxf(o0.z + bi0.z, 0.f); o0.w = fmaxf(o0.w + bi0.w, 0.f);
                o1.x = fmaxf(o1.x + bi1.x, 0.f); o1.y = fmaxf(o1.y + bi1.y, 0.f);
                o1.z = fmaxf(o1.z + bi1.z, 0.f); o1.w = fmaxf(o1.w + bi1.w, 0.f);
            }
            float* dst = Cout + (((size_t)b * H_ + h) * L_ + row) * DK_ + d;
            *(float4*)dst = o0;
            *(float4*)(dst + 4) = o1;
        }
}
#define GEMM3_SMEM (2 * 64 * 128 * (int)sizeof(float))

// ===================================================================
// Kernel 4+5 fused: fc GEMM + residual + LayerNorm.
// Tile 128r x 256c (full rows!), 512 threads, 8x8 micro.
//   ry = tid&15 (rows as above), cx = tid>>4 (0..31, cols cx*8)
// grid (mt=4, b=64)
// ===================================================================
__global__ void __launch_bounds__(512, 1) gemm_ln_kernel(
    const float* __restrict__ A, const float* __restrict__ Bw,
    const float* __restrict__ resid,
    const float* __restrict__ gam, const float* __restrict__ bet,
    float* __restrict__ out)
{
    extern __shared__ float sm[];
    float* sAT = sm;              // [64][128]  (8192 f) — reused as sS
    float* sB  = sm + 64 * 128;   // [64][256]  (16384 f) — reused as sS2

    int tid = threadIdx.x;
    int ry = tid & 15, cx = tid >> 4;   // cx 0..31
    int mt = blockIdx.x, b = blockIdx.y;
    int r0 = mt * 128;
    const float* Ab = A + (size_t)b * L_ * F_;

    float2 acc[2][4][4];
    #pragma unroll
    for (int h2 = 0; h2 < 2; h2++)
        #pragma unroll
        for (int rr = 0; rr < 4; rr++)
            #pragma unroll
            for (int cc = 0; cc < 4; cc++)
                acc[h2][rr][cc] = make_float2(0.f, 0.f);

    for (int k0 = 0; k0 < F_; k0 += 64) {
        __syncthreads();
        // stage A transposed (2048 float4 slots / 512 thr = 4 each)
        #pragma unroll
        for (int it = 0; it < 4; it++) {
            int idx = tid + it * 512;
            int r = idx & 127, kb = idx >> 7;       // kb 0..15
            int row = r0 + r;
            float4 v = make_float4(0.f, 0.f, 0.f, 0.f);
            if (row < L_) v = *(const float4*)(Ab + (size_t)row * F_ + k0 + kb * 4);
            sAT[(kb * 4 + 0) * 128 + r] = v.x;
            sAT[(kb * 4 + 1) * 128 + r] = v.y;
            sAT[(kb * 4 + 2) * 128 + r] = v.z;
            sAT[(kb * 4 + 3) * 128 + r] = v.w;
        }
        // stage B natural [64][256] (4096 float4 slots / 512 = 8 each)
        #pragma unroll
        for (int it = 0; it < 8; it++) {
            int idx = tid + it * 512;
            int kk = idx >> 6, c4 = (idx & 63) * 4;
            float4 v = *(const float4*)(Bw + (size_t)(k0 + kk) * F_ + c4);
            *(float4*)&sB[kk * 256 + c4] = v;
        }
        __syncthreads();

        #pragma unroll 8
        for (int kk = 0; kk < 64; kk++) {
            float4 a0 = *(const float4*)&sAT[kk * 128 + ry * 4];
            float4 a1 = *(const float4*)&sAT[kk * 128 + 64 + ry * 4];
            float4 b0 = *(const float4*)&sB[kk * 256 + cx * 8];
            float4 b1 = *(const float4*)&sB[kk * 256 + cx * 8 + 4];
            float2 bc0 = make_float2(b0.x, b0.y), bc1 = make_float2(b0.z, b0.w);
            float2 bc2 = make_float2(b1.x, b1.y), bc3 = make_float2(b1.z, b1.w);
            float av[2][4] = { {a0.x, a0.y, a0.z, a0.w}, {a1.x, a1.y, a1.z, a1.w} };
            #pragma unroll
            for (int h2 = 0; h2 < 2; h2++)
                #pragma unroll
                for (int rr = 0; rr < 4; rr++) {
                    float2 ap = make_float2(av[h2][rr], av[h2][rr]);
                    acc[h2][rr][0] = ffma2(ap, bc0, acc[h2][rr][0]);
                    acc[h2][rr][1] = ffma2(ap, bc1, acc[h2][rr][1]);
                    acc[h2][rr][2] = ffma2(ap, bc2, acc[h2][rr][2]);
                    acc[h2][rr][3] = ffma2(ap, bc3, acc[h2][rr][3]);
                }
        }
    }

    // ---- epilogue: +residual, then LayerNorm over the 256-col row ----
    __syncthreads();            // inner-loop smem reads done; reuse sAT/sB
    float* sS  = sAT;           // [128][33] partial sums (+slot 32 = mu)
    float* sS2 = sB;            // [128][33] partial sumsq (+slot 32 = inv)
    int c = cx * 8;
    const float* rb = resid + ((size_t)b * L_) * F_;

    #pragma unroll
    for (int h2 = 0; h2 < 2; h2++)
        #pragma unroll
        for (int rr = 0; rr < 4; rr++) {
            int rt = h2 * 64 + ry * 4 + rr;
            int row = r0 + rt;
            float s = 0.f, s2 = 0.f;
            if (row < L_) {
                float4 rv0 = *(const float4*)(rb + (size_t)row * F_ + c);
                float4 rv1 = *(const float4*)(rb + (size_t)row * F_ + c + 4);
                acc[h2][rr][0].x += rv0.x; acc[h2][rr][0].y += rv0.y;
                acc[h2][rr][1].x += rv0.z; acc[h2][rr][1].y += rv0.w;
                acc[h2][rr][2].x += rv1.x; acc[h2][rr][2].y += rv1.y;
                acc[h2][rr][3].x += rv1.z; acc[h2][rr][3].y += rv1.w;
                #pragma unroll
                for (int cc = 0; cc < 4; cc++) {
                    s  += acc[h2][rr][cc].x + acc[h2][rr][cc].y;
                    s2 += acc[h2][rr][cc].x * acc[h2][rr][cc].x
                        + acc[h2][rr][cc].y * acc[h2][rr][cc].y;
                }
            }
            sS[rt * 33 + cx]  = s;
            sS2[rt * 33 + cx] = s2;
        }
    __syncthreads();
    if (tid < 128) {
        float s = 0.f, s2 = 0.f;
        #pragma unroll
        for (int x = 0; x < 32; x++) { s += sS[tid * 33 + x]; s2 += sS2[tid * 33 + x]; }
        float mu = s * (1.f / F_);
        float var = s2 * (1.f / F_) - mu * mu;
        sS[tid * 33 + 32]  = mu;
        sS2[tid * 33 + 32] = rsqrtf(var + 1e-6f);
    }
    __syncthreads();

    float4 g0 = *(const float4*)(gam + c), g1 = *(const float4*)(gam + c + 4);
    float4 e0 = *(const float4*)(bet + c), e1 = *(const float4*)(bet + c + 4);
    #pragma unroll
    for (int h2 = 0; h2 < 2; h2++)
        #pragma unroll
        for (int rr = 0; rr < 4; rr++) {
            int rt = h2 * 64 + ry * 4 + rr;
            int row = r0 + rt;
            if (row >= L_) continue;
            float mu = sS[rt * 33 + 32], inv = sS2[rt * 33 + 32];
            float4 o0, o1;
            o0.x = (acc[h2][rr][0].x - mu) * inv * g0.x + e0.x;
            o0.y = (acc[h2][rr][0].y - mu) * inv * g0.y + e0.y;
            o0.z = (acc[h2][rr][1].x - mu) * inv * g0.z + e0.z;
            o0.w = (acc[h2][rr][1].y - mu) * inv * g0.w + e0.w;
            o1.x = (acc[h2][rr][2].x - mu) * inv * g1.x + e1.x;
            o1.y = (acc[h2][rr][2].y - mu) * inv * g1.y + e1.y;
            o1.z = (acc[h2][rr][3].x - mu) * inv * g1.z + e1.z;
            o1.w = (acc[h2][rr][3].y - mu) * inv * g1.w + e1.w;
            float* dst = out + ((size_t)b * L_ + row) * F_ + c;
            *(float4*)dst = o0;
            *(float4*)(dst + 4) = o1;
        }
}
#define GEMMLN_SMEM ((64 * 128 + 64 * 256) * (int)sizeof(float))

// ===================================================================
// Kernel 3 (v3): attention — unchanged from round 11 (374 us, proven)
// ===================================================================
#define A_WT   0                      // [64][128]
#define A_W2   (A_WT + 64 * 128)      // [64][128]
#define A_V    (A_W2 + 64 * 128)      // [128][64]
#define A_PT   (A_V  + 128 * 64)      // [128][128]
#define A_B2   (A_PT + 128 * 128)     // [512]
#define A_TOT  (A_B2 + 512)

__global__ void __launch_bounds__(256, 1) attn_v3_kernel(
    const float* __restrict__ w2, const float* __restrict__ b2,
    const float* __restrict__ weight, const float* __restrict__ vh,
    float* __restrict__ attnout)
{
    extern __shared__ float sm[];
    int tid = threadIdx.x;
    int ry = tid & 15, jx = tid >> 4;
    int bh = blockIdx.x, mt = blockIdx.y;
    int r0 = mt * 128;
    const float* wbase = weight + (size_t)bh * L_ * DK_;
    const float* vbase = vh + (size_t)bh * L_ * DK_;

    for (int i = tid; i < 512; i += 256)
        sm[A_B2 + i] = (i < L_) ? b2[i] : -1.0e30f;

    #pragma unroll
    for (int it = 0; it < 8; it++) {
        int idx = tid + it * 256;
        int r = idx >> 4;
        int d4 = (idx & 15) * 4;
        int row = r0 + r;
        float4 v = make_float4(0.f, 0.f, 0.f, 0.f);
        if (row < L_) v = *(const float4*)(wbase + (size_t)row * DK_ + d4);
        sm[A_WT + (d4 + 0) * 128 + r] = v.x;
        sm[A_WT + (d4 + 1) * 128 + r] = v.y;
        sm[A_WT + (d4 + 2) * 128 + r] = v.z;
        sm[A_WT + (d4 + 3) * 128 + r] = v.w;
    }

    float2 accO[2][4][2];
    float lsumP[2][4];
    #pragma unroll
    for (int h2 = 0; h2 < 2; h2++)
        #pragma unroll
        for (int rr = 0; rr < 4; rr++) {
            lsumP[h2][rr] = 0.f;
            accO[h2][rr][0] = make_float2(0.f, 0.f);
            accO[h2][rr][1] = make_float2(0.f, 0.f);
        }

    for (int jt = 0; jt < 4; jt++) {
        int j0 = jt * 128;
        __syncthreads();

        #pragma unroll
        for (int it = 0; it < 32; it++) {
            int idx = tid + it * 256;
            int d = idx >> 7, jj = idx & 127;
            int j = j0 + jj;
            sm[A_W2 + d * 128 + jj] = (j < L_) ? w2[(size_t)d * L_ + j] : 0.f;
        }
        #pragma unroll
        for (int it = 0; it < 8; it++) {
            int idx = tid + it * 256;
            int jj = idx >> 4;
            int d4 = (idx & 15) * 4;
            int j = j0 + jj;
            float4 v = make_float4(0.f, 0.f, 0.f, 0.f);
            if (j < L_) v = *(const float4*)(vbase + (size_t)j * DK_ + d4);
            *(float4*)&sm[A_V + jj * 64 + d4] = v;
        }
        __syncthreads();

        float2 accS[2][4][4];
        {
            float4 bb0 = *(const float4*)&sm[A_B2 + j0 + jx * 8];
            float4 bb1 = *(const float4*)&sm[A_B2 + j0 + jx * 8 + 4];
            float2 bc[4] = { make_float2(bb0.x, bb0.y), make_float2(bb0.z, bb0.w),
                             make_float2(bb1.x, bb1.y), make_float2(bb1.z, bb1.w) };
            #pragma unroll
            for (int h2 = 0; h2 < 2; h2++)
                #pragma unroll
                for (int rr = 0; rr < 4; rr++)
                    #pragma unroll
                    for (int cc = 0; cc < 4; cc++)
                        accS[h2][rr][cc] = bc[cc];
        }
        #pragma unroll 4
        for (int d = 0; d < 64; d++) {
            float4 a0 = *(const float4*)&sm[A_WT + d * 128 + ry * 4];
            float4 a1 = *(const float4*)&sm[A_WT + d * 128 + 64 + ry * 4];
            float4 b0 = *(const float4*)&sm[A_W2 + d * 128 + jx * 8];
            float4 b1 = *(const float4*)&sm[A_W2 + d * 128 + jx * 8 + 4];
            float2 bc0 = make_float2(b0.x, b0.y), bc1 = make_float2(b0.z, b0.w);
            float2 bc2 = make_float2(b1.x, b1.y), bc3 = make_float2(b1.z, b1.w);
            float av[2][4] = { {a0.x, a0.y, a0.z, a0.w}, {a1.x, a1.y, a1.z, a1.w} };
            #pragma unroll
            for (int h2 = 0; h2 < 2; h2++)
                #pragma unroll
                for (int rr = 0; rr < 4; rr++) {
                    float2 ap = make_float2(av[h2][rr], av[h2][rr]);
                    accS[h2][rr][0] = ffma2(ap, bc0, accS[h2][rr][0]);
                    accS[h2][rr][1] = ffma2(ap, bc1, accS[h2][rr][1]);
                    accS[h2][rr][2] = ffma2(ap, bc2, accS[h2][rr][2]);
                    accS[h2][rr][3] = ffma2(ap, bc3, accS[h2][rr][3]);
                }
        }

        #pragma unroll
        for (int h2 = 0; h2 < 2; h2++)
            #pragma unroll
            for (int rr = 0; rr < 4; rr++) {
                float s = 0.f;
                #pragma unroll
                for (int cc = 0; cc < 4; cc++) {
                    float px = __expf(accS[h2][rr][cc].x);
                    float py = __expf(accS[h2][rr][cc].y);
                    accS[h2][rr][cc] = make_float2(px, py);
                    s += px + py;
                }
                lsumP[h2][rr] += s;
            }

        #pragma unroll
        for (int jj = 0; jj < 8; jj++) {
            int cc = jj >> 1;
            float4 c0, c1;
            if (jj & 1) {
                c0 = make_float4(accS[0][0][cc].y, accS[0][1][cc].y, accS[0][2][cc].y, accS[0][3][cc].y);
                c1 = make_float4(accS[1][0][cc].y, accS[1][1][cc].y, accS[1][2][cc].y, accS[1][3][cc].y);
            } else {
                c0 = make_float4(accS[0][0][cc].x, accS[0][1][cc].x, accS[0][2][cc].x, accS[0][3][cc].x);
                c1 = make_float4(accS[1][0][cc].x, accS[1][1][cc].x, accS[1][2][cc].x, accS[1][3][cc].x);
            }
            int j = jx * 8 + jj;
            *(float4*)&sm[A_PT + j * 128 + ry * 4]      = c0;
            *(float4*)&sm[A_PT + j * 128 + 64 + ry * 4] = c1;
        }
        __syncthreads();

        #pragma unroll 4
        for (int j = 0; j < 128; j++) {
            float4 a0 = *(const float4*)&sm[A_PT + j * 128 + ry * 4];
            float4 a1 = *(const float4*)&sm[A_PT + j * 128 + 64 + ry * 4];
            float4 bv = *(const float4*)&sm[A_V + j * 64 + jx * 4];
            float2 q0 = make_float2(bv.x, bv.y), q1 = make_float2(bv.z, bv.w);
            float av[2][4] = { {a0.x, a0.y, a0.z, a0.w}, {a1.x, a1.y, a1.z, a1.w} };
            #pragma unroll
            for (int h2 = 0; h2 < 2; h2++)
                #pragma unroll
                for (int rr = 0; rr < 4; rr++) {
                    float2 pp = make_float2(av[h2][rr], av[h2][rr]);
                    accO[h2][rr][0] = ffma2(pp, q0, accO[h2][rr][0]);
                    accO[h2][rr][1] = ffma2(pp, q1, accO[h2][rr][1]);
                }
        }
    }

    __syncthreads();
    float* sRed = &sm[A_W2];
    #pragma unroll
    for (int h2 = 0; h2 < 2; h2++)
        #pragma unroll
        for (int rr = 0; rr < 4; rr++) {
            int rt = h2 * 64 + ry * 4 + rr;
            sRed[rt * 17 + jx] = lsumP[h2][rr];
        }
    __syncthreads();
    float* sInv = &sm[A_B2];
    if (tid < 128) {
        float s = 0.f;
        #pragma unroll
        for (int x = 0; x < 16; x++) s += sRed[tid * 17 + x];
        sInv[tid] = 1.f / s;
    }
    __syncthreads();

    int b = bh >> 2, h = bh & 3;
    #pragma unroll
    for (int h2 = 0; h2 < 2; h2++)
        #pragma unroll
        for (int rr = 0; rr < 4; rr++) {
            int rt = h2 * 64 + ry * 4 + rr;
            int row = r0 + rt;
            if (row < L_) {
                float inv = sInv[rt];
                float4 o = make_float4(accO[h2][rr][0].x * inv, accO[h2][rr][0].y * inv,
                                       accO[h2][rr][1].x * inv, accO[h2][rr][1].y * inv);
                *(float4*)(attnout + ((size_t)b * L_ + row) * F_ + h * DK_ + jx * 4) = o;
            }
        }
}
#define ATTN_SMEM (A_TOT * (int)sizeof(float))

// ===================================================================
// launch
// ===================================================================
extern "C" void kernel_launch(void* const* d_in, const int* in_sizes, int n_in,
                              void* d_out, int out_size) {
    (void)in_sizes; (void)n_in; (void)out_size;
    const float* q    = (const float*)d_in[0];
    const float* v    = (const float*)d_in[2];
    const float* w_qs = (const float*)d_in[3];
    const float* w_vs = (const float*)d_in[4];
    const float* w1   = (const float*)d_in[5];
    const float* b1   = (const float*)d_in[6];
    const float* w2   = (const float*)d_in[7];
    const float* b2   = (const float*)d_in[8];
    const float* fc_w = (const float*)d_in[9];
    const float* ln_g = (const float*)d_in[10];
    const float* ln_b = (const float*)d_in[11];
    float* out = (float*)d_out;

    float *Wc_p, *weight_p, *vh_p, *attn_p;
    cudaGetSymbolAddress((void**)&Wc_p,     g_Wc);
    cudaGetSymbolAddress((void**)&weight_p, g_weight);
    cudaGetSymbolAddress((void**)&vh_p,     g_vh);
    cudaGetSymbolAddress((void**)&attn_p,   g_attnout);

    cudaFuncSetAttribute(gemm_v3_kernel<0>, cudaFuncAttributeMaxDynamicSharedMemorySize, GEMM3_SMEM);
    cudaFuncSetAttribute(gemm_v3_kernel<1>, cudaFuncAttributeMaxDynamicSharedMemorySize, GEMM3_SMEM);
    cudaFuncSetAttribute(gemm_ln_kernel,    cudaFuncAttributeMaxDynamicSharedMemorySize, GEMMLN_SMEM);
    cudaFuncSetAttribute(attn_v3_kernel,    cudaFuncAttributeMaxDynamicSharedMemorySize, ATTN_SMEM);

    // 0) combined q-projection weight
    wc_kernel<<<256, 256>>>(w_qs, w1);

    dim3 gg3(2, 4, 64);
    // 1) weight = relu(q @ Wc + b1) -> [b][h][l][d]
    gemm_v3_kernel<1><<<gg3, 256, GEMM3_SMEM>>>(q, Wc_p, b1, weight_p);
    // 2) vh = v @ w_vs -> [b][h][l][d]
    gemm_v3_kernel<0><<<gg3, 256, GEMM3_SMEM>>>(v, w_vs, nullptr, vh_p);
    // 3) fused synthesizer attention
    attn_v3_kernel<<<dim3(BH_, 4), 256, ATTN_SMEM>>>(w2, b2, weight_p, vh_p, attn_p);
    // 4+5) out = LayerNorm(attnout @ fc_w + q)
    gemm_ln_kernel<<<dim3(4, 64), 512, GEMMLN_SMEM>>>(attn_p, fc_w, q, ln_g, ln_b, out);
}